// round 1
// baseline (speedup 1.0000x reference)
#include <cuda_runtime.h>
#include <cfloat>
#include <climits>
#include <math.h>

// Problem constants
#define Bc 4
#define Nc 500
#define Cc 80
#define Tc 28
#define TTc 784
#define Mc 16
#define Hc 800
#define Wc 800
#define EPSc 1e-8f
#define CANDK 10

// Scratch (device globals; no allocation allowed)
__device__ float g_gm[Bc * Mc * TTc];       // cropped+binarized gt masks
__device__ float g_gmsum[Bc * Mc];          // per gt mask sums
__device__ float g_inter[Bc * Nc * Mc];     // sum_t ms[n,cls(m),t]*gm[m,t]
__device__ float g_msum[Bc * Nc * Mc];      // sum_t ms[n,cls(m),t]
__device__ float g_cost[Bc * Nc * Mc];      // SimOTA cost matrix
__device__ float g_ious[Bc * Nc * Mc];      // raw IoUs (valid-gated)
__device__ int   g_valid[Bc * Nc];          // per-anchor validity
__device__ int   g_colsel[Bc * Mc * CANDK]; // selected anchor indices per gt (or -1)
__device__ double g_acc[5];                 // cls, l1, giou, mask, n_fg

__device__ __forceinline__ float sigm(float x) { return 1.0f / (1.0f + expf(-x)); }

// ---------------------------------------------------------------------------
// K1: ROIAlign-style crop of gt_masks [B,M,H,W] -> gm [B,M,28*28], binarized.
// Also zeroes the loss accumulators (runs before k_loss in stream order).
// ---------------------------------------------------------------------------
__global__ void k_crop(const float* __restrict__ gt_boxes,
                       const float* __restrict__ gt_masks) {
    int bm = blockIdx.x;  // b*M + m
    if (bm == 0 && threadIdx.x < 5) g_acc[threadIdx.x] = 0.0;

    float x1 = gt_boxes[bm * 4 + 0];
    float y1 = gt_boxes[bm * 4 + 1];
    float x2 = gt_boxes[bm * 4 + 2];
    float y2 = gt_boxes[bm * 4 + 3];
    const float* mask = gt_masks + (size_t)bm * Hc * Wc;

    __shared__ float ssum[256];
    float acc = 0.0f;
    for (int pix = threadIdx.x; pix < TTc; pix += blockDim.x) {
        int j = pix / Tc;   // row index (y)
        int i = pix % Tc;   // col index (x)
        // match jax op order: x1 + ((arange+0.5)*(x2-x1))/T - 0.5
        float y = y1 + ((j + 0.5f) * (y2 - y1)) / (float)Tc - 0.5f;
        float x = x1 + ((i + 0.5f) * (x2 - x1)) / (float)Tc - 0.5f;
        float y0f = floorf(y), x0f = floorf(x);
        int y0 = (int)y0f, x0 = (int)x0f;
        float fy = y - y0f, fx = x - x0f;
        float v00 = 0.f, v01 = 0.f, v10 = 0.f, v11 = 0.f;
        bool yi0 = (y0 >= 0 && y0 < Hc);
        bool yi1 = (y0 + 1 >= 0 && y0 + 1 < Hc);
        bool xi0 = (x0 >= 0 && x0 < Wc);
        bool xi1 = (x0 + 1 >= 0 && x0 + 1 < Wc);
        if (yi0 && xi0) v00 = mask[(size_t)y0 * Wc + x0];
        if (yi0 && xi1) v01 = mask[(size_t)y0 * Wc + x0 + 1];
        if (yi1 && xi0) v10 = mask[(size_t)(y0 + 1) * Wc + x0];
        if (yi1 && xi1) v11 = mask[(size_t)(y0 + 1) * Wc + x0 + 1];
        float s = v00 * (1.f - fy) * (1.f - fx) + v01 * (1.f - fy) * fx +
                  v10 * fy * (1.f - fx) + v11 * fy * fx;
        float bin = (s >= 0.5f) ? 1.0f : 0.0f;
        g_gm[bm * TTc + pix] = bin;
        acc += bin;
    }
    ssum[threadIdx.x] = acc;
    __syncthreads();
    for (int s = 128; s > 0; s >>= 1) {
        if (threadIdx.x < s) ssum[threadIdx.x] += ssum[threadIdx.x + s];
        __syncthreads();
    }
    if (threadIdx.x == 0) g_gmsum[bm] = ssum[0];
}

// ---------------------------------------------------------------------------
// K2 (hot): per (b,n) block. 16 warps: warp m computes mask dot + sum at the
// gt class of m. Then threads 0..15 build cost & iou matrices.
// ---------------------------------------------------------------------------
__global__ void __launch_bounds__(512)
k_cost(const float* __restrict__ logits, const float* __restrict__ boxes,
       const float* __restrict__ masks, const int* __restrict__ gtc,
       const float* __restrict__ gtb, const float* __restrict__ img) {
    int bn = blockIdx.x;            // b*N + n
    int b = bn / Nc;
    int wid = threadIdx.x >> 5;
    int lane = threadIdx.x & 31;

    __shared__ float s_i[Mc], s_s[Mc];

    {
        int m = wid;
        int c = gtc[b * Mc + m];
        const float* mp = masks + ((size_t)bn * Cc + c) * TTc;
        const float* gp = g_gm + (b * Mc + m) * TTc;
        float si = 0.f, ii = 0.f;
        for (int t = lane; t < TTc; t += 32) {
            float s = sigm(mp[t]);
            si += s;
            ii += s * gp[t];
        }
        for (int o = 16; o; o >>= 1) {
            si += __shfl_xor_sync(0xffffffffu, si, o);
            ii += __shfl_xor_sync(0xffffffffu, ii, o);
        }
        if (lane == 0) {
            s_i[m] = ii;
            s_s[m] = si;
            g_inter[bn * Mc + m] = ii;
            g_msum[bn * Mc + m] = si;
        }
    }
    __syncthreads();

    if (threadIdx.x < Mc) {
        int m = threadIdx.x;
        float bx1 = boxes[bn * 4 + 0], by1 = boxes[bn * 4 + 1];
        float bx2 = boxes[bn * 4 + 2], by2 = boxes[bn * 4 + 3];
        float cx = (bx1 + bx2) * 0.5f, cy = (by1 + by2) * 0.5f;
        float gx1 = gtb[(b * Mc + m) * 4 + 0], gy1 = gtb[(b * Mc + m) * 4 + 1];
        float gx2 = gtb[(b * Mc + m) * 4 + 2], gy2 = gtb[(b * Mc + m) * 4 + 3];

        bool inbox = (cx > gx1) && (cx < gx2) && (cy > gy1) && (cy < gy2);
        float gcx = (gx1 + gx2) * 0.5f, gcy = (gy1 + gy2) * 0.5f;
        float gw = gx2 - gx1, gh = gy2 - gy1;
        bool inctr = (fabsf(cx - gcx) < 0.25f * gw) && (fabsf(cy - gcy) < 0.25f * gh);
        bool inboth = inbox && inctr;
        unsigned ball = __ballot_sync(0xffffu, inbox || inctr);
        bool valid = (ball != 0u);

        // classification cost
        int c2 = gtc[b * Mc + m];
        float lo = logits[(size_t)bn * Cc + c2];
        float p = sigm(lo);
        float neg = -logf((1.0f - p) + EPSc) * 0.75f * p * p;
        float pos = -logf(p + EPSc) * 0.25f * (1.0f - p) * (1.0f - p);
        float clsc = 2.0f * (pos - neg);

        // normalized boxes
        float i0 = img[b * 4 + 0], i1 = img[b * 4 + 1], i2 = img[b * 4 + 2], i3 = img[b * 4 + 3];
        float nx1 = bx1 / i0, ny1 = by1 / i1, nx2 = bx2 / i2, ny2 = by2 / i3;
        float mx1 = gx1 / i0, my1 = gy1 / i1, mx2 = gx2 / i2, my2 = gy2 / i3;

        float l1c = 5.0f * (fabsf(nx1 - mx1) + fabsf(ny1 - my1) +
                            fabsf(nx2 - mx2) + fabsf(ny2 - my2));

        // giou (normalized)
        float ltx = fmaxf(nx1, mx1), lty = fmaxf(ny1, my1);
        float rbx = fminf(nx2, mx2), rby = fminf(ny2, my2);
        float iw = fmaxf(rbx - ltx, 0.f), ih = fmaxf(rby - lty, 0.f);
        float inter = iw * ih;
        float a1 = (nx2 - nx1) * (ny2 - ny1);
        float a2 = (mx2 - mx1) * (my2 - my1);
        float uni = a1 + a2 - inter;
        float iou = inter / (uni + EPSc);
        float ex = fmaxf(fmaxf(nx2, mx2) - fminf(nx1, mx1), 0.f);
        float ey = fmaxf(fmaxf(ny2, my2) - fminf(ny1, my1), 0.f);
        float enc = ex * ey;
        float giou = iou - (enc - uni) / (enc + EPSc);
        float giouc = 2.0f * (1.0f - giou);

        // mask cost (dice)
        float mu = s_s[m] + g_gmsum[b * Mc + m] + EPSc;
        float maskc = 5.0f * (1.0f - 2.0f * s_i[m] / mu);

        // match the reference's f32 left-assoc accumulation order
        float cost = clsc + l1c;
        cost = cost + giouc;
        cost = cost + maskc;
        cost = cost + (inboth ? 0.0f : 1e5f);
        cost = cost + (valid ? 0.0f : 1e9f);
        g_cost[bn * Mc + m] = cost;

        // raw (pixel-space) IoU, valid-gated
        float rltx = fmaxf(bx1, gx1), rlty = fmaxf(by1, gy1);
        float rrbx = fminf(bx2, gx2), rrby = fminf(by2, gy2);
        float riw = fmaxf(rrbx - rltx, 0.f), rih = fmaxf(rrby - rlty, 0.f);
        float rinter = riw * rih;
        float ra1 = (bx2 - bx1) * (by2 - by1);
        float ra2 = (gx2 - gx1) * (gy2 - gy1);
        float runi = ra1 + ra2 - rinter;
        float riou = rinter / (runi + EPSc);
        g_ious[bn * Mc + m] = riou * (valid ? 1.0f : 0.0f);

        if (m == 0) g_valid[bn] = valid ? 1 : 0;
    }
}

// ---------------------------------------------------------------------------
// K3: per (b,m) block. dyn_k from top-10 IoUs, then select dyn_k lowest-cost
// anchors (tie-break: lowest index, matching jax.lax.top_k stability).
// ---------------------------------------------------------------------------
__global__ void __launch_bounds__(512)
k_match() {
    int bm = blockIdx.x;  // b*M + m
    int b = bm / Mc;
    int m = bm % Mc;
    int tid = threadIdx.x;

    __shared__ float sc[Nc];
    __shared__ float si2[Nc];
    __shared__ float sv[512];
    __shared__ int sidx[512];
    __shared__ int sdyn;

    for (int i = tid; i < Nc; i += 512) {
        sc[i] = g_cost[(b * Nc + i) * Mc + m];
        si2[i] = g_ious[(b * Nc + i) * Mc + m];
    }
    __syncthreads();

    // --- dyn_k: sum of top-10 ious (descending order sum, like top_k) ---
    float ksum = 0.0f;  // only tid 0's copy is used
    for (int r = 0; r < CANDK; r++) {
        float v; int id;
        if (tid < Nc) { v = si2[tid]; id = tid; }
        else { v = -FLT_MAX; id = INT_MAX; }
        sv[tid] = v; sidx[tid] = id;
        __syncthreads();
        for (int s = 256; s > 0; s >>= 1) {
            if (tid < s) {
                if (sv[tid + s] > sv[tid] ||
                    (sv[tid + s] == sv[tid] && sidx[tid + s] < sidx[tid])) {
                    sv[tid] = sv[tid + s];
                    sidx[tid] = sidx[tid + s];
                }
            }
            __syncthreads();
        }
        if (tid == 0) {
            ksum += sv[0];
            si2[sidx[0]] = -FLT_MAX;
        }
        __syncthreads();
    }
    if (tid == 0) {
        int dk = (int)ksum;   // trunc toward zero, ksum >= 0
        if (dk < 1) dk = 1;
        if (dk > CANDK) dk = CANDK;
        sdyn = dk;
    }
    __syncthreads();
    int dyn = sdyn;

    // --- top-CANDK lowest cost, tie -> lowest index ---
    for (int r = 0; r < CANDK; r++) {
        float v; int id;
        if (tid < Nc) { v = sc[tid]; id = tid; }
        else { v = FLT_MAX; id = INT_MAX; }
        sv[tid] = v; sidx[tid] = id;
        __syncthreads();
        for (int s = 256; s > 0; s >>= 1) {
            if (tid < s) {
                if (sv[tid + s] < sv[tid] ||
                    (sv[tid + s] == sv[tid] && sidx[tid + s] < sidx[tid])) {
                    sv[tid] = sv[tid + s];
                    sidx[tid] = sidx[tid + s];
                }
            }
            __syncthreads();
        }
        if (tid == 0) {
            int ii = sidx[0];
            g_colsel[bm * CANDK + r] = (r < dyn) ? ii : -1;
            sc[ii] = FLT_MAX;
        }
        __syncthreads();
    }
}

// ---------------------------------------------------------------------------
// K4: warp per (b,n). Resolve matching, compute losses, accumulate.
// ---------------------------------------------------------------------------
__global__ void __launch_bounds__(256)
k_loss(const float* __restrict__ logits, const float* __restrict__ boxes,
       const int* __restrict__ gtc, const float* __restrict__ gtb,
       const float* __restrict__ img) {
    __shared__ double sacc[5];
    int tid = threadIdx.x;
    if (tid < 5) sacc[tid] = 0.0;
    __syncthreads();

    int wid = tid >> 5;
    int lane = tid & 31;
    int g = blockIdx.x * 8 + wid;  // b*N + n  (grid sized exactly)
    int b = g / Nc;
    int n = g % Nc;

    int matched = 0;
    int fg = 0;
    if (lane == 0) {
        int cnt = 0, firstm = -1;
        for (int m = 0; m < Mc; m++) {
            bool member = false;
            #pragma unroll
            for (int r = 0; r < CANDK; r++) {
                int s = g_colsel[(b * Mc + m) * CANDK + r];
                if (s == n) { member = true; }
            }
            if (member) {
                cnt++;
                if (firstm < 0) firstm = m;
            }
        }
        int valid = g_valid[g];
        if (cnt > 1) {
            // argmin over cost row (first-min)
            float bestv = FLT_MAX;
            int bestm = 0;
            for (int m = 0; m < Mc; m++) {
                float cv = g_cost[g * Mc + m];
                if (cv < bestv) { bestv = cv; bestm = m; }
            }
            matched = bestm;
        } else {
            matched = (cnt >= 1) ? firstm : 0;
        }
        fg = (cnt > 0 && valid) ? 1 : 0;
    }
    matched = __shfl_sync(0xffffffffu, matched, 0);
    fg = __shfl_sync(0xffffffffu, fg, 0);

    if (fg) {
        int tcls = gtc[b * Mc + matched];
        // focal over C classes (warp-parallel)
        float fsum = 0.0f;
        for (int c = lane; c < Cc; c += 32) {
            float l = logits[(size_t)g * Cc + c];
            float tgt = (c == tcls) ? 1.0f : 0.0f;
            float p = sigm(l);
            float ce = fmaxf(l, 0.0f) - l * tgt + log1pf(expf(-fabsf(l)));
            float pt = p * tgt + (1.0f - p) * (1.0f - tgt);
            float om = 1.0f - pt;
            float w = 0.25f * tgt + 0.75f * (1.0f - tgt);
            fsum += ce * om * om * w;
        }
        for (int o = 16; o; o >>= 1) fsum += __shfl_xor_sync(0xffffffffu, fsum, o);

        if (lane == 0) {
            float i0 = img[b * 4 + 0], i1 = img[b * 4 + 1], i2 = img[b * 4 + 2], i3 = img[b * 4 + 3];
            float nx1 = boxes[g * 4 + 0] / i0, ny1 = boxes[g * 4 + 1] / i1;
            float nx2 = boxes[g * 4 + 2] / i2, ny2 = boxes[g * 4 + 3] / i3;
            int gm_i = b * Mc + matched;
            float mx1 = gtb[gm_i * 4 + 0] / i0, my1 = gtb[gm_i * 4 + 1] / i1;
            float mx2 = gtb[gm_i * 4 + 2] / i2, my2 = gtb[gm_i * 4 + 3] / i3;

            float l1v = fabsf(nx1 - mx1) + fabsf(ny1 - my1) +
                        fabsf(nx2 - mx2) + fabsf(ny2 - my2);

            float ltx = fmaxf(nx1, mx1), lty = fmaxf(ny1, my1);
            float rbx = fminf(nx2, mx2), rby = fminf(ny2, my2);
            float iw = fmaxf(rbx - ltx, 0.f), ih = fmaxf(rby - lty, 0.f);
            float inter = iw * ih;
            float a1 = (nx2 - nx1) * (ny2 - ny1);
            float a2 = (mx2 - mx1) * (my2 - my1);
            float uni = a1 + a2 - inter;
            float iou = inter / (uni + EPSc);
            float ex = fmaxf(fmaxf(nx2, mx2) - fminf(nx1, mx1), 0.f);
            float ey = fmaxf(fmaxf(ny2, my2) - fminf(ny1, my1), 0.f);
            float enc = ex * ey;
            float giou = iou - (enc - uni) / (enc + EPSc);
            float gv = 1.0f - giou;

            float mi = g_inter[g * Mc + matched];
            float msv = g_msum[g * Mc + matched];
            float mu = msv + g_gmsum[gm_i] + EPSc;
            float mkv = 1.0f - 2.0f * mi / mu;

            atomicAdd(&sacc[0], (double)fsum);
            atomicAdd(&sacc[1], (double)l1v);
            atomicAdd(&sacc[2], (double)gv);
            atomicAdd(&sacc[3], (double)mkv);
            atomicAdd(&sacc[4], 1.0);
        }
    }
    __syncthreads();
    if (tid < 5) atomicAdd(&g_acc[tid], sacc[tid]);
}

__global__ void k_final(float* out) {
    if (threadIdx.x == 0) {
        double nt = g_acc[4];
        out[0] = (float)(2.0 * g_acc[0] / nt);
        out[1] = (float)(5.0 * g_acc[1] / nt);
        out[2] = (float)(2.0 * g_acc[2] / nt);
        out[3] = (float)(5.0 * g_acc[3] / nt);
    }
}

extern "C" void kernel_launch(void* const* d_in, const int* in_sizes, int n_in,
                              void* d_out, int out_size) {
    const float* pred_logits = (const float*)d_in[0];
    const float* pred_boxes  = (const float*)d_in[1];
    const float* pred_masks  = (const float*)d_in[2];
    const int*   gt_classes  = (const int*)d_in[3];
    const float* gt_boxes    = (const float*)d_in[4];
    const float* gt_masks    = (const float*)d_in[5];
    const float* image_size  = (const float*)d_in[6];
    float* out = (float*)d_out;

    k_crop<<<Bc * Mc, 256>>>(gt_boxes, gt_masks);
    k_cost<<<Bc * Nc, 512>>>(pred_logits, pred_boxes, pred_masks,
                             gt_classes, gt_boxes, image_size);
    k_match<<<Bc * Mc, 512>>>();
    k_loss<<<(Bc * Nc) / 8, 256>>>(pred_logits, pred_boxes,
                                   gt_classes, gt_boxes, image_size);
    k_final<<<1, 32>>>(out);
}

// round 2
// speedup vs baseline: 2.0224x; 2.0224x over previous
#include <cuda_runtime.h>
#include <cfloat>
#include <climits>
#include <math.h>

// Problem constants
#define Bc 4
#define Nc 500
#define Cc 80
#define Tc 28
#define TTc 784
#define Mc 16
#define Hc 800
#define Wc 800
#define EPSc 1e-8f
#define CANDK 10

// Scratch (device globals; no allocation allowed)
__device__ float g_gm[Bc * Mc * TTc];       // cropped+binarized gt masks
__device__ float g_gmsum[Bc * Mc];          // per gt mask sums
__device__ float g_inter[Bc * Nc * Mc];     // sum_t ms[n,cls(m),t]*gm[m,t]
__device__ float g_msum[Bc * Nc * Mc];      // sum_t ms[n,cls(m),t]
__device__ float g_cost[Bc * Nc * Mc];      // SimOTA cost matrix
__device__ float g_ious[Bc * Nc * Mc];      // raw IoUs (valid-gated)
__device__ int   g_valid[Bc * Nc];          // per-anchor validity
__device__ int   g_colsel[Bc * Mc * CANDK]; // selected anchor indices per gt (or -1)
__device__ double g_acc[5];                 // cls, l1, giou, mask, n_fg
__device__ unsigned g_done;                 // ticket for final reduction

__device__ __forceinline__ float fsigm(float x) {
    return __fdividef(1.0f, 1.0f + __expf(-x));
}

// ---------------------------------------------------------------------------
// K1: ROIAlign-style crop of gt_masks [B,M,H,W] -> gm [B,M,28*28], binarized.
// Also zeroes the loss accumulators / ticket (runs before k_loss in stream).
// ---------------------------------------------------------------------------
__global__ void k_crop(const float* __restrict__ gt_boxes,
                       const float* __restrict__ gt_masks) {
    int bm = blockIdx.x;  // b*M + m
    if (bm == 0 && threadIdx.x < 5) g_acc[threadIdx.x] = 0.0;
    if (bm == 0 && threadIdx.x == 5) g_done = 0u;

    float x1 = gt_boxes[bm * 4 + 0];
    float y1 = gt_boxes[bm * 4 + 1];
    float x2 = gt_boxes[bm * 4 + 2];
    float y2 = gt_boxes[bm * 4 + 3];
    const float* mask = gt_masks + (size_t)bm * Hc * Wc;

    __shared__ float ssum[256];
    float acc = 0.0f;
    for (int pix = threadIdx.x; pix < TTc; pix += blockDim.x) {
        int j = pix / Tc;   // row index (y)
        int i = pix % Tc;   // col index (x)
        float y = y1 + ((j + 0.5f) * (y2 - y1)) / (float)Tc - 0.5f;
        float x = x1 + ((i + 0.5f) * (x2 - x1)) / (float)Tc - 0.5f;
        float y0f = floorf(y), x0f = floorf(x);
        int y0 = (int)y0f, x0 = (int)x0f;
        float fy = y - y0f, fx = x - x0f;
        float v00 = 0.f, v01 = 0.f, v10 = 0.f, v11 = 0.f;
        bool yi0 = (y0 >= 0 && y0 < Hc);
        bool yi1 = (y0 + 1 >= 0 && y0 + 1 < Hc);
        bool xi0 = (x0 >= 0 && x0 < Wc);
        bool xi1 = (x0 + 1 >= 0 && x0 + 1 < Wc);
        if (yi0 && xi0) v00 = __ldg(&mask[(size_t)y0 * Wc + x0]);
        if (yi0 && xi1) v01 = __ldg(&mask[(size_t)y0 * Wc + x0 + 1]);
        if (yi1 && xi0) v10 = __ldg(&mask[(size_t)(y0 + 1) * Wc + x0]);
        if (yi1 && xi1) v11 = __ldg(&mask[(size_t)(y0 + 1) * Wc + x0 + 1]);
        float s = v00 * (1.f - fy) * (1.f - fx) + v01 * (1.f - fy) * fx +
                  v10 * fy * (1.f - fx) + v11 * fy * fx;
        float bin = (s >= 0.5f) ? 1.0f : 0.0f;
        g_gm[bm * TTc + pix] = bin;
        acc += bin;
    }
    ssum[threadIdx.x] = acc;
    __syncthreads();
    for (int s = 128; s > 0; s >>= 1) {
        if (threadIdx.x < s) ssum[threadIdx.x] += ssum[threadIdx.x + s];
        __syncthreads();
    }
    if (threadIdx.x == 0) g_gmsum[bm] = ssum[0];
}

// ---------------------------------------------------------------------------
// K2 (hot): per (b,n) block. 16 warps: warp m computes mask dot + sum at the
// gt class of m (float4 streams + fast sigmoid). Then threads 0..15 build the
// cost & iou matrices.
// ---------------------------------------------------------------------------
__global__ void __launch_bounds__(512)
k_cost(const float* __restrict__ logits, const float* __restrict__ boxes,
       const float* __restrict__ masks, const int* __restrict__ gtc,
       const float* __restrict__ gtb, const float* __restrict__ img) {
    int bn = blockIdx.x;            // b*N + n
    int b = bn / Nc;
    int wid = threadIdx.x >> 5;
    int lane = threadIdx.x & 31;

    __shared__ float s_i[Mc], s_s[Mc];

    {
        int m = wid;
        int c = gtc[b * Mc + m];
        const float4* mp = (const float4*)(masks + ((size_t)bn * Cc + c) * TTc);
        const float4* gp = (const float4*)(g_gm + (b * Mc + m) * TTc);
        float si = 0.f, ii = 0.f;
        // 784 floats = 196 float4
        #pragma unroll 7
        for (int j = lane; j < 196; j += 32) {
            float4 mv = __ldg(&mp[j]);
            float4 gv = gp[j];
            float s0 = fsigm(mv.x), s1 = fsigm(mv.y);
            float s2 = fsigm(mv.z), s3 = fsigm(mv.w);
            si += s0 + s1 + s2 + s3;
            ii += s0 * gv.x + s1 * gv.y + s2 * gv.z + s3 * gv.w;
        }
        for (int o = 16; o; o >>= 1) {
            si += __shfl_xor_sync(0xffffffffu, si, o);
            ii += __shfl_xor_sync(0xffffffffu, ii, o);
        }
        if (lane == 0) {
            s_i[m] = ii;
            s_s[m] = si;
            g_inter[bn * Mc + m] = ii;
            g_msum[bn * Mc + m] = si;
        }
    }
    __syncthreads();

    if (threadIdx.x < Mc) {
        int m = threadIdx.x;
        float bx1 = boxes[bn * 4 + 0], by1 = boxes[bn * 4 + 1];
        float bx2 = boxes[bn * 4 + 2], by2 = boxes[bn * 4 + 3];
        float cx = (bx1 + bx2) * 0.5f, cy = (by1 + by2) * 0.5f;
        float gx1 = gtb[(b * Mc + m) * 4 + 0], gy1 = gtb[(b * Mc + m) * 4 + 1];
        float gx2 = gtb[(b * Mc + m) * 4 + 2], gy2 = gtb[(b * Mc + m) * 4 + 3];

        bool inbox = (cx > gx1) && (cx < gx2) && (cy > gy1) && (cy < gy2);
        float gcx = (gx1 + gx2) * 0.5f, gcy = (gy1 + gy2) * 0.5f;
        float gw = gx2 - gx1, gh = gy2 - gy1;
        bool inctr = (fabsf(cx - gcx) < 0.25f * gw) && (fabsf(cy - gcy) < 0.25f * gh);
        bool inboth = inbox && inctr;
        unsigned ball = __ballot_sync(0xffffu, inbox || inctr);
        bool valid = (ball != 0u);

        // classification cost
        int c2 = gtc[b * Mc + m];
        float lo = logits[(size_t)bn * Cc + c2];
        float p = fsigm(lo);
        float neg = -logf((1.0f - p) + EPSc) * 0.75f * p * p;
        float pos = -logf(p + EPSc) * 0.25f * (1.0f - p) * (1.0f - p);
        float clsc = 2.0f * (pos - neg);

        // normalized boxes
        float i0 = img[b * 4 + 0], i1 = img[b * 4 + 1], i2 = img[b * 4 + 2], i3 = img[b * 4 + 3];
        float nx1 = bx1 / i0, ny1 = by1 / i1, nx2 = bx2 / i2, ny2 = by2 / i3;
        float mx1 = gx1 / i0, my1 = gy1 / i1, mx2 = gx2 / i2, my2 = gy2 / i3;

        float l1c = 5.0f * (fabsf(nx1 - mx1) + fabsf(ny1 - my1) +
                            fabsf(nx2 - mx2) + fabsf(ny2 - my2));

        // giou (normalized)
        float ltx = fmaxf(nx1, mx1), lty = fmaxf(ny1, my1);
        float rbx = fminf(nx2, mx2), rby = fminf(ny2, my2);
        float iw = fmaxf(rbx - ltx, 0.f), ih = fmaxf(rby - lty, 0.f);
        float inter = iw * ih;
        float a1 = (nx2 - nx1) * (ny2 - ny1);
        float a2 = (mx2 - mx1) * (my2 - my1);
        float uni = a1 + a2 - inter;
        float iou = inter / (uni + EPSc);
        float ex = fmaxf(fmaxf(nx2, mx2) - fminf(nx1, mx1), 0.f);
        float ey = fmaxf(fmaxf(ny2, my2) - fminf(ny1, my1), 0.f);
        float enc = ex * ey;
        float giou = iou - (enc - uni) / (enc + EPSc);
        float giouc = 2.0f * (1.0f - giou);

        // mask cost (dice)
        float mu = s_s[m] + g_gmsum[b * Mc + m] + EPSc;
        float maskc = 5.0f * (1.0f - 2.0f * s_i[m] / mu);

        float cost = clsc + l1c;
        cost = cost + giouc;
        cost = cost + maskc;
        cost = cost + (inboth ? 0.0f : 1e5f);
        cost = cost + (valid ? 0.0f : 1e9f);
        g_cost[bn * Mc + m] = cost;

        // raw (pixel-space) IoU, valid-gated
        float rltx = fmaxf(bx1, gx1), rlty = fmaxf(by1, gy1);
        float rrbx = fminf(bx2, gx2), rrby = fminf(by2, gy2);
        float riw = fmaxf(rrbx - rltx, 0.f), rih = fmaxf(rrby - rlty, 0.f);
        float rinter = riw * rih;
        float ra1 = (bx2 - bx1) * (by2 - by1);
        float ra2 = (gx2 - gx1) * (gy2 - gy1);
        float runi = ra1 + ra2 - rinter;
        float riou = rinter / (runi + EPSc);
        g_ious[bn * Mc + m] = riou * (valid ? 1.0f : 0.0f);

        if (m == 0) g_valid[bn] = valid ? 1 : 0;
    }
}

// ---------------------------------------------------------------------------
// K3: one warp per (b,m) column, whole column register-resident.
// dyn_k from top-10 IoUs (desc, lowest-index tie-break), then select dyn_k
// lowest-cost anchors (lowest-index tie-break). Zero barriers.
// ---------------------------------------------------------------------------
__global__ void __launch_bounds__(32)
k_match() {
    int bm = blockIdx.x;  // b*M + m
    int b = bm / Mc;
    int m = bm % Mc;
    int lane = threadIdx.x;

    float cv[16], iv[16];
    #pragma unroll
    for (int r = 0; r < 16; r++) {
        int i = lane + 32 * r;
        if (i < Nc) {
            cv[r] = g_cost[(b * Nc + i) * Mc + m];
            iv[r] = g_ious[(b * Nc + i) * Mc + m];
        } else {
            cv[r] = FLT_MAX;
            iv[r] = -FLT_MAX;
        }
    }

    // dyn_k = trunc(sum of top-10 ious), clamp >= 1
    float ksum = 0.0f;
    for (int k = 0; k < CANDK; k++) {
        float best = -FLT_MAX; int bi = INT_MAX;
        #pragma unroll
        for (int r = 0; r < 16; r++) {
            if (iv[r] > best) { best = iv[r]; bi = lane + 32 * r; }
        }
        #pragma unroll
        for (int o = 16; o; o >>= 1) {
            float ov = __shfl_xor_sync(0xffffffffu, best, o);
            int oi = __shfl_xor_sync(0xffffffffu, bi, o);
            if (ov > best || (ov == best && oi < bi)) { best = ov; bi = oi; }
        }
        ksum += best;
        if ((bi & 31) == lane) iv[bi >> 5] = -FLT_MAX;
    }
    int dyn = (int)ksum;
    if (dyn < 1) dyn = 1;
    if (dyn > CANDK) dyn = CANDK;

    // top-CANDK lowest cost
    for (int k = 0; k < CANDK; k++) {
        float best = FLT_MAX; int bi = INT_MAX;
        #pragma unroll
        for (int r = 0; r < 16; r++) {
            if (cv[r] < best) { best = cv[r]; bi = lane + 32 * r; }
        }
        #pragma unroll
        for (int o = 16; o; o >>= 1) {
            float ov = __shfl_xor_sync(0xffffffffu, best, o);
            int oi = __shfl_xor_sync(0xffffffffu, bi, o);
            if (ov < best || (ov == best && oi < bi)) { best = ov; bi = oi; }
        }
        if (lane == 0) g_colsel[bm * CANDK + k] = (k < dyn) ? bi : -1;
        if ((bi & 31) == lane) cv[bi >> 5] = FLT_MAX;
    }
}

// ---------------------------------------------------------------------------
// K4: warp per (b,n). Membership via 16-lane ballot; row argmin via shuffle.
// Losses accumulated into shared doubles -> global; last block writes out.
// ---------------------------------------------------------------------------
__global__ void __launch_bounds__(256)
k_loss(const float* __restrict__ logits, const float* __restrict__ boxes,
       const int* __restrict__ gtc, const float* __restrict__ gtb,
       const float* __restrict__ img, float* __restrict__ out) {
    __shared__ double sacc[5];
    int tid = threadIdx.x;
    if (tid < 5) sacc[tid] = 0.0;
    __syncthreads();

    int wid = tid >> 5;
    int lane = tid & 31;
    int g = blockIdx.x * 8 + wid;  // b*N + n  (grid sized exactly)
    int b = g / Nc;
    int n = g % Nc;

    // membership: lane m<16 checks column m
    bool member = false;
    if (lane < Mc) {
        #pragma unroll
        for (int r = 0; r < CANDK; r++) {
            if (g_colsel[(b * Mc + lane) * CANDK + r] == n) member = true;
        }
    }
    unsigned mb = __ballot_sync(0xffffffffu, member) & 0xffffu;
    int cnt = __popc(mb);
    int matched;
    if (cnt > 1) {
        // first-min over the cost row
        float v = (lane < Mc) ? g_cost[g * Mc + lane] : FLT_MAX;
        int bi = (lane < Mc) ? lane : INT_MAX;
        #pragma unroll
        for (int o = 16; o; o >>= 1) {
            float ov = __shfl_xor_sync(0xffffffffu, v, o);
            int oi = __shfl_xor_sync(0xffffffffu, bi, o);
            if (ov < v || (ov == v && oi < bi)) { v = ov; bi = oi; }
        }
        matched = bi;
    } else {
        matched = (cnt >= 1) ? (__ffs(mb) - 1) : 0;
    }
    int fg = (cnt > 0) && g_valid[g];

    if (fg) {
        int tcls = gtc[b * Mc + matched];
        // focal over C classes (warp-parallel)
        float fsum = 0.0f;
        for (int c = lane; c < Cc; c += 32) {
            float l = logits[(size_t)g * Cc + c];
            float tgt = (c == tcls) ? 1.0f : 0.0f;
            float p = fsigm(l);
            float ce = fmaxf(l, 0.0f) - l * tgt + log1pf(__expf(-fabsf(l)));
            float pt = p * tgt + (1.0f - p) * (1.0f - tgt);
            float om = 1.0f - pt;
            float w = 0.25f * tgt + 0.75f * (1.0f - tgt);
            fsum += ce * om * om * w;
        }
        #pragma unroll
        for (int o = 16; o; o >>= 1) fsum += __shfl_xor_sync(0xffffffffu, fsum, o);

        if (lane == 0) {
            float i0 = img[b * 4 + 0], i1 = img[b * 4 + 1], i2 = img[b * 4 + 2], i3 = img[b * 4 + 3];
            float nx1 = boxes[g * 4 + 0] / i0, ny1 = boxes[g * 4 + 1] / i1;
            float nx2 = boxes[g * 4 + 2] / i2, ny2 = boxes[g * 4 + 3] / i3;
            int gm_i = b * Mc + matched;
            float mx1 = gtb[gm_i * 4 + 0] / i0, my1 = gtb[gm_i * 4 + 1] / i1;
            float mx2 = gtb[gm_i * 4 + 2] / i2, my2 = gtb[gm_i * 4 + 3] / i3;

            float l1v = fabsf(nx1 - mx1) + fabsf(ny1 - my1) +
                        fabsf(nx2 - mx2) + fabsf(ny2 - my2);

            float ltx = fmaxf(nx1, mx1), lty = fmaxf(ny1, my1);
            float rbx = fminf(nx2, mx2), rby = fminf(ny2, my2);
            float iw = fmaxf(rbx - ltx, 0.f), ih = fmaxf(rby - lty, 0.f);
            float inter = iw * ih;
            float a1 = (nx2 - nx1) * (ny2 - ny1);
            float a2 = (mx2 - mx1) * (my2 - my1);
            float uni = a1 + a2 - inter;
            float iou = inter / (uni + EPSc);
            float ex = fmaxf(fmaxf(nx2, mx2) - fminf(nx1, mx1), 0.f);
            float ey = fmaxf(fmaxf(ny2, my2) - fminf(ny1, my1), 0.f);
            float enc = ex * ey;
            float giou = iou - (enc - uni) / (enc + EPSc);
            float gv = 1.0f - giou;

            float mi = g_inter[g * Mc + matched];
            float msv = g_msum[g * Mc + matched];
            float mu = msv + g_gmsum[gm_i] + EPSc;
            float mkv = 1.0f - 2.0f * mi / mu;

            atomicAdd(&sacc[0], (double)fsum);
            atomicAdd(&sacc[1], (double)l1v);
            atomicAdd(&sacc[2], (double)gv);
            atomicAdd(&sacc[3], (double)mkv);
            atomicAdd(&sacc[4], 1.0);
        }
    }
    __syncthreads();
    if (tid < 5) atomicAdd(&g_acc[tid], sacc[tid]);
    __syncthreads();
    if (tid == 0) {
        __threadfence();
        unsigned ticket = atomicAdd(&g_done, 1u);
        if (ticket == gridDim.x - 1) {
            __threadfence();
            double nt = g_acc[4];
            out[0] = (float)(2.0 * g_acc[0] / nt);
            out[1] = (float)(5.0 * g_acc[1] / nt);
            out[2] = (float)(2.0 * g_acc[2] / nt);
            out[3] = (float)(5.0 * g_acc[3] / nt);
        }
    }
}

extern "C" void kernel_launch(void* const* d_in, const int* in_sizes, int n_in,
                              void* d_out, int out_size) {
    const float* pred_logits = (const float*)d_in[0];
    const float* pred_boxes  = (const float*)d_in[1];
    const float* pred_masks  = (const float*)d_in[2];
    const int*   gt_classes  = (const int*)d_in[3];
    const float* gt_boxes    = (const float*)d_in[4];
    const float* gt_masks    = (const float*)d_in[5];
    const float* image_size  = (const float*)d_in[6];
    float* out = (float*)d_out;

    k_crop<<<Bc * Mc, 256>>>(gt_boxes, gt_masks);
    k_cost<<<Bc * Nc, 512>>>(pred_logits, pred_boxes, pred_masks,
                             gt_classes, gt_boxes, image_size);
    k_match<<<Bc * Mc, 32>>>();
    k_loss<<<(Bc * Nc) / 8, 256>>>(pred_logits, pred_boxes,
                                   gt_classes, gt_boxes, image_size, out);
}